// round 2
// baseline (speedup 1.0000x reference)
#include <cuda_runtime.h>
#include <cstdint>

// ---------------------------------------------------------------------------
// Problem constants
// ---------------------------------------------------------------------------
#define NN_MAX 25000
#define NE_MAX 200000
#define HDIM   192
#define OUTF   64

// scratch layout (floats)
constexpr size_t OFF_NR  = 0;
constexpr size_t OFF_NI  = OFF_NR  + (size_t)NN_MAX * 64;
constexpr size_t OFF_ER  = OFF_NI  + (size_t)NN_MAX * 64;
constexpr size_t OFF_EI  = OFF_ER  + (size_t)NE_MAX * 64;
constexpr size_t OFF_NSR = OFF_EI  + (size_t)NE_MAX * 64;
constexpr size_t OFF_ESR = OFF_NSR + (size_t)NN_MAX * 64;
constexpr size_t OFF_NSI = OFF_ESR + (size_t)NN_MAX * 64;
constexpr size_t OFF_ESI = OFF_NSI + (size_t)NN_MAX * 64;
constexpr size_t SCRATCH_FLOATS = OFF_ESI + (size_t)NN_MAX * 64;

__device__ __align__(256) float g_scratch[SCRATCH_FLOATS];
__device__ int g_is64;

// ---------------------------------------------------------------------------
// f32x2 helpers (packed fp32 pair: .x = real channel, .y = imag channel)
// ---------------------------------------------------------------------------
__device__ __forceinline__ unsigned long long pack2(float a, float b) {
    unsigned long long r;
    asm("mov.b64 %0, {%1,%2};" : "=l"(r) : "f"(a), "f"(b));
    return r;
}
__device__ __forceinline__ void unpack2(unsigned long long v, float& a, float& b) {
    asm("mov.b64 {%0,%1}, %2;" : "=f"(a), "=f"(b) : "l"(v));
}
__device__ __forceinline__ void fma2(unsigned long long& d,
                                     unsigned long long a, unsigned long long b) {
    asm("fma.rn.f32x2 %0, %1, %2, %0;" : "+l"(d) : "l"(a), "l"(b));
}

// ---------------------------------------------------------------------------
// edge_index dtype detection (int64 vs int32). For int64 (values < 2^31,
// little-endian) all odd 32-bit words are 0; for int32 they are node indices.
// ---------------------------------------------------------------------------
__global__ void detect_kernel(const unsigned int* __restrict__ w) {
    unsigned int v = w[2 * threadIdx.x + 1] | w[2 * threadIdx.x + 65];
    unsigned int any = __ballot_sync(0xffffffffu, v != 0u);
    if (threadIdx.x == 0) g_is64 = (any == 0u) ? 1 : 0;
}

__device__ __forceinline__ int eidx_get(const void* __restrict__ p, int i) {
    if (g_is64) return (int)((const long long*)p)[i];
    return ((const int*)p)[i];
}

// ---------------------------------------------------------------------------
// zero aggregation buffers
// ---------------------------------------------------------------------------
__global__ void zero_kernel(float4* __restrict__ p, int n4) {
    int i = blockIdx.x * blockDim.x + threadIdx.x;
    if (i < n4) p[i] = make_float4(0.f, 0.f, 0.f, 0.f);
}

// ---------------------------------------------------------------------------
// lin64: Y = X @ W^T + b for both channels packed as f32x2.
// 64 rows / block, 256 threads (16x16), thread tile 4 rows x 4 cols.
// dyn smem: Xs (64*64 ull) + Ws (64*65 float)
// ---------------------------------------------------------------------------
constexpr int LIN_SMEM = 64 * 64 * 8 + 64 * 65 * 4;

__global__ __launch_bounds__(256) void lin64_kernel(
    int M,
    const float* __restrict__ Xa, const float* __restrict__ Xb,
    const float* __restrict__ W,  const float* __restrict__ bias,
    float* __restrict__ Ya, float* __restrict__ Yb)
{
    extern __shared__ char smraw[];
    unsigned long long* Xs = (unsigned long long*)smraw;   // [64][64]
    float* Ws = (float*)(Xs + 64 * 64);                    // [64][65]

    int tid = threadIdx.x;
    int r0  = blockIdx.x * 64;

    for (int i = tid; i < 4096; i += 256) {
        int n = i >> 6, k = i & 63;
        Ws[n * 65 + k] = W[i];
    }
    for (int i = tid; i < 4096; i += 256) {
        int r = i >> 6, k = i & 63, gr = r0 + r;
        float a = 0.f, b = 0.f;
        if (gr < M) { a = Xa[gr * 64 + k]; b = Xb[gr * 64 + k]; }
        Xs[i] = pack2(a, b);
    }
    __syncthreads();

    int tx = tid & 15, ty = tid >> 4;
    unsigned long long acc[4][4];
#pragma unroll
    for (int j = 0; j < 4; j++) {
        float bv = bias[tx + 16 * j];
        unsigned long long pb = pack2(bv, bv);
#pragma unroll
        for (int i = 0; i < 4; i++) acc[i][j] = pb;
    }

#pragma unroll 8
    for (int k = 0; k < 64; k++) {
        unsigned long long xv[4], wv[4];
#pragma unroll
        for (int i = 0; i < 4; i++) xv[i] = Xs[(ty * 4 + i) * 64 + k];
#pragma unroll
        for (int j = 0; j < 4; j++) {
            float w = Ws[(tx + 16 * j) * 65 + k];
            wv[j] = pack2(w, w);
        }
#pragma unroll
        for (int i = 0; i < 4; i++)
#pragma unroll
            for (int j = 0; j < 4; j++) fma2(acc[i][j], xv[i], wv[j]);
    }

#pragma unroll
    for (int i = 0; i < 4; i++) {
        int gr = r0 + ty * 4 + i;
        if (gr < M) {
#pragma unroll
            for (int j = 0; j < 4; j++) {
                float a, b;
                unpack2(acc[i][j], a, b);
                Ya[gr * 64 + tx + 16 * j] = a;
                Yb[gr * 64 + tx + 16 * j] = b;
            }
        }
    }
}

// ---------------------------------------------------------------------------
// scatter: for each edge e: ns[row] += n[col]; es[row] += e  (real & imag)
// 16 threads per edge, 4 features each (float4 loads, scalar red.global.add)
// ---------------------------------------------------------------------------
__global__ __launch_bounds__(256) void scatter_kernel(
    int NE, const void* __restrict__ eidx,
    const float* __restrict__ nr, const float* __restrict__ ni,
    const float* __restrict__ er, const float* __restrict__ ei,
    float* __restrict__ nsr, float* __restrict__ esr,
    float* __restrict__ nsi, float* __restrict__ esi)
{
    int gid = blockIdx.x * blockDim.x + threadIdx.x;
    int e = gid >> 4;
    if (e >= NE) return;
    int q = (gid & 15) * 4;
    int row = eidx_get(eidx, 2 * e);
    int col = eidx_get(eidx, 2 * e + 1);

    const float4 a = *(const float4*)(nr + col * 64 + q);
    const float4 b = *(const float4*)(er + e   * 64 + q);
    const float4 c = *(const float4*)(ni + col * 64 + q);
    const float4 d = *(const float4*)(ei + e   * 64 + q);

    float* p1 = nsr + row * 64 + q;
    float* p2 = esr + row * 64 + q;
    float* p3 = nsi + row * 64 + q;
    float* p4 = esi + row * 64 + q;
    atomicAdd(p1 + 0, a.x); atomicAdd(p1 + 1, a.y); atomicAdd(p1 + 2, a.z); atomicAdd(p1 + 3, a.w);
    atomicAdd(p2 + 0, b.x); atomicAdd(p2 + 1, b.y); atomicAdd(p2 + 2, b.z); atomicAdd(p2 + 3, b.w);
    atomicAdd(p3 + 0, c.x); atomicAdd(p3 + 1, c.y); atomicAdd(p3 + 2, c.z); atomicAdd(p3 + 3, c.w);
    atomicAdd(p4 + 0, d.x); atomicAdd(p4 + 1, d.y); atomicAdd(p4 + 2, d.z); atomicAdd(p4 + 3, d.w);
}

// ---------------------------------------------------------------------------
// Fused MLP: 3x (192->192 + LeakyReLU) + (192->64), real+imag packed f32x2.
// MODE 0 (node): x = [s0[r], s1[r], s2[r]]       (nr, ns, es)
// MODE 1 (edge): x = [s0[e], s1[row(e)], s1[col(e)]]   (er, h, h)
// 64 rows / block, 256 threads (16x16), thread tile 4 rows x 12 cols.
// dyn smem: Xs (64*192 ull, activations stay resident) + Wc (192*17 ull,
//           k-chunked weight tile pre-splatted to f32x2)
// ---------------------------------------------------------------------------
constexpr int MLP_SMEM = (64 * HDIM + HDIM * 17) * 8;

template <int MODE>
__global__ __launch_bounds__(256) void mlp_kernel(
    int M,
    const float* __restrict__ s0r, const float* __restrict__ s0i,
    const float* __restrict__ s1r, const float* __restrict__ s1i,
    const float* __restrict__ s2r, const float* __restrict__ s2i,
    const void* __restrict__ eidx,
    const float* __restrict__ W,  const float* __restrict__ B,
    const float* __restrict__ alpha,
    const float* __restrict__ Wout, const float* __restrict__ bout,
    float* __restrict__ outR, float* __restrict__ outI)
{
    extern __shared__ char smraw[];
    unsigned long long* Xs = (unsigned long long*)smraw;   // [64][192]
    unsigned long long* Wc = Xs + 64 * HDIM;               // [192][17] (pad 17)

    int tid = threadIdx.x;
    int r0  = blockIdx.x * 64;

    // ---- fill activation tile (gather + pack) ----
    for (int idx = tid; idx < 64 * HDIM; idx += 256) {
        int r = idx / HDIM, k = idx - r * HDIM;
        int gr = r0 + r;
        float a = 0.f, b = 0.f;
        if (gr < M) {
            int src = k >> 6, f = k & 63;
            if (MODE == 0) {
                const float* pr = (src == 0) ? s0r : (src == 1 ? s1r : s2r);
                const float* pi = (src == 0) ? s0i : (src == 1 ? s1i : s2i);
                a = pr[gr * 64 + f];
                b = pi[gr * 64 + f];
            } else {
                if (src == 0) {
                    a = s0r[gr * 64 + f];
                    b = s0i[gr * 64 + f];
                } else {
                    int node = eidx_get(eidx, 2 * gr + (src - 1)); // 1->row, 2->col
                    a = s1r[node * 64 + f];
                    b = s1i[node * 64 + f];
                }
            }
        }
        Xs[idx] = pack2(a, b);
    }

    int tx = tid & 15, ty = tid >> 4;

    // ---- 3 hidden layers ----
    for (int l = 0; l < 3; l++) {
        const float* Wl = W + l * HDIM * HDIM;
        const float* bl = B + l * HDIM;
        float al = alpha[l];

        unsigned long long acc[4][12];
#pragma unroll
        for (int j = 0; j < 12; j++) {
            float bv = bl[tx + 16 * j];
            unsigned long long pb = pack2(bv, bv);
#pragma unroll
            for (int i = 0; i < 4; i++) acc[i][j] = pb;
        }

        for (int kt = 0; kt < HDIM; kt += 16) {
            __syncthreads();
            for (int idx = tid; idx < HDIM * 16; idx += 256) {
                int n = idx >> 4, kl = idx & 15;
                float w = Wl[n * HDIM + kt + kl];
                Wc[n * 17 + kl] = pack2(w, w);
            }
            __syncthreads();
#pragma unroll
            for (int kl = 0; kl < 16; kl++) {
                unsigned long long xv[4], wv[12];
#pragma unroll
                for (int i = 0; i < 4; i++) xv[i] = Xs[(ty * 4 + i) * HDIM + kt + kl];
#pragma unroll
                for (int j = 0; j < 12; j++) wv[j] = Wc[(tx + 16 * j) * 17 + kl];
#pragma unroll
                for (int i = 0; i < 4; i++)
#pragma unroll
                    for (int j = 0; j < 12; j++) fma2(acc[i][j], xv[i], wv[j]);
            }
        }

        __syncthreads();
#pragma unroll
        for (int i = 0; i < 4; i++)
#pragma unroll
            for (int j = 0; j < 12; j++) {
                float a, b;
                unpack2(acc[i][j], a, b);
                a = (a >= 0.f) ? a : al * a;
                b = (b >= 0.f) ? b : al * b;
                Xs[(ty * 4 + i) * HDIM + tx + 16 * j] = pack2(a, b);
            }
    }

    // ---- output layer 192 -> 64 ----
    unsigned long long oacc[4][4];
#pragma unroll
    for (int j = 0; j < 4; j++) {
        float bv = bout[tx + 16 * j];
        unsigned long long pb = pack2(bv, bv);
#pragma unroll
        for (int i = 0; i < 4; i++) oacc[i][j] = pb;
    }

    for (int kt = 0; kt < HDIM; kt += 16) {
        __syncthreads();
        for (int idx = tid; idx < OUTF * 16; idx += 256) {
            int n = idx >> 4, kl = idx & 15;
            float w = Wout[n * HDIM + kt + kl];
            Wc[n * 17 + kl] = pack2(w, w);
        }
        __syncthreads();
#pragma unroll
        for (int kl = 0; kl < 16; kl++) {
            unsigned long long xv[4], wv[4];
#pragma unroll
            for (int i = 0; i < 4; i++) xv[i] = Xs[(ty * 4 + i) * HDIM + kt + kl];
#pragma unroll
            for (int j = 0; j < 4; j++) wv[j] = Wc[(tx + 16 * j) * 17 + kl];
#pragma unroll
            for (int i = 0; i < 4; i++)
#pragma unroll
                for (int j = 0; j < 4; j++) fma2(oacc[i][j], xv[i], wv[j]);
        }
    }

#pragma unroll
    for (int i = 0; i < 4; i++) {
        int gr = r0 + ty * 4 + i;
        if (gr < M) {
#pragma unroll
            for (int j = 0; j < 4; j++) {
                float a, b;
                unpack2(oacc[i][j], a, b);
                outR[gr * 64 + tx + 16 * j] = a;
                outI[gr * 64 + tx + 16 * j] = b;
            }
        }
    }
}

// ---------------------------------------------------------------------------
// launch
// ---------------------------------------------------------------------------
extern "C" void kernel_launch(void* const* d_in, const int* in_sizes, int n_in,
                              void* d_out, int out_size)
{
    const float* node_real = (const float*)d_in[0];
    const float* node_imag = (const float*)d_in[1];
    const float* edge_real = (const float*)d_in[2];
    const float* edge_imag = (const float*)d_in[3];
    const void*  edge_index = d_in[4];
    const float* Wn = (const float*)d_in[5];
    const float* bn = (const float*)d_in[6];
    const float* We = (const float*)d_in[7];
    const float* be = (const float*)d_in[8];
    const float* node_W    = (const float*)d_in[9];
    const float* node_b    = (const float*)d_in[10];
    const float* node_alpha= (const float*)d_in[11];
    const float* node_outW = (const float*)d_in[12];
    const float* node_outb = (const float*)d_in[13];
    const float* edge_W    = (const float*)d_in[14];
    const float* edge_b    = (const float*)d_in[15];
    const float* edge_alpha= (const float*)d_in[16];
    const float* edge_outW = (const float*)d_in[17];
    const float* edge_outb = (const float*)d_in[18];

    int Nn = in_sizes[0] / 64;
    int Ne = in_sizes[2] / 64;

    float* scratch = nullptr;
    cudaGetSymbolAddress((void**)&scratch, g_scratch);
    float* nr  = scratch + OFF_NR;
    float* ni  = scratch + OFF_NI;
    float* er  = scratch + OFF_ER;
    float* ei  = scratch + OFF_EI;
    float* nsr = scratch + OFF_NSR;
    float* esr = scratch + OFF_ESR;
    float* nsi = scratch + OFF_NSI;
    float* esi = scratch + OFF_ESI;

    float* outp = (float*)d_out;
    float* hr   = outp;
    float* hi   = outp + (size_t)Nn * 64;
    float* outr = outp + (size_t)2 * Nn * 64;
    float* outi = outr + (size_t)Ne * 64;

    cudaFuncSetAttribute(lin64_kernel, cudaFuncAttributeMaxDynamicSharedMemorySize, LIN_SMEM);
    cudaFuncSetAttribute(mlp_kernel<0>, cudaFuncAttributeMaxDynamicSharedMemorySize, MLP_SMEM);
    cudaFuncSetAttribute(mlp_kernel<1>, cudaFuncAttributeMaxDynamicSharedMemorySize, MLP_SMEM);

    // 1) detect edge_index dtype
    detect_kernel<<<1, 32>>>((const unsigned int*)edge_index);

    // 2) zero aggregation region (full max extent; layout uses NN_MAX strides)
    int aggN4 = (int)(4 * (size_t)NN_MAX * 64 / 4);
    zero_kernel<<<(aggN4 + 255) / 256, 256>>>((float4*)nsr, aggN4);

    // 3) node / edge input linears (real+imag fused per f32x2 lane)
    lin64_kernel<<<(Nn + 63) / 64, 256, LIN_SMEM>>>(Nn, node_real, node_imag, Wn, bn, nr, ni);
    lin64_kernel<<<(Ne + 63) / 64, 256, LIN_SMEM>>>(Ne, edge_real, edge_imag, We, be, er, ei);

    // 4) edge scatter-aggregation
    int sthreads = Ne * 16;
    scatter_kernel<<<(sthreads + 255) / 256, 256>>>(Ne, edge_index, nr, ni, er, ei,
                                                    nsr, esr, nsi, esi);

    // 5) node MLP -> hr, hi (directly into d_out)
    mlp_kernel<0><<<(Nn + 63) / 64, 256, MLP_SMEM>>>(
        Nn, nr, ni, nsr, nsi, esr, esi, nullptr,
        node_W, node_b, node_alpha, node_outW, node_outb, hr, hi);

    // 6) edge MLP (gathers hr/hi by row/col) -> outr, outi
    mlp_kernel<1><<<(Ne + 63) / 64, 256, MLP_SMEM>>>(
        Ne, er, ei, hr, hi, hr, hi, edge_index,
        edge_W, edge_b, edge_alpha, edge_outW, edge_outb, outr, outi);
}